// round 13
// baseline (speedup 1.0000x reference)
#include <cuda_runtime.h>
#include <cuda_fp16.h>
#include <math.h>
#include <stdint.h>

#define B_SZ 4096
#define K_SZ 256
#define N_SZ 8

// ---------------------------------------------------------------------------
// Scratch (device globals; allocations are banned)
// ---------------------------------------------------------------------------
__device__ __align__(256) float  g_L1[B_SZ * 256];
__device__ __align__(256) float  g_L2[B_SZ * 256];
__device__ __align__(256) float  g_L3[B_SZ * 256];
__device__ __align__(256) float  g_Y[B_SZ * 256];    // raw bilinear output
__device__ __align__(256) float  g_R1[B_SZ * 256];
__device__ __align__(256) float  g_R2[B_SZ * 256];
__device__ __align__(256) __half g_Sh[B_SZ * 512];
__device__ __align__(256) __half g_Vh[B_SZ * 512];
__device__ __align__(256) __half g_Oh[B_SZ * 512];   // also phase-3 OUTh dump
__device__ __align__(256) __half g_R1h[B_SZ * 256];
__device__ __align__(256) __half g_R2h[B_SZ * 256];
__device__ __align__(256) __half g_T1h[256u * 512u * 512u];
__device__ __align__(256) __half g_T2h[256u * 512u * 512u];
__device__ __align__(256) __half g_T3h[256u * 256u * 256u];
__device__ __align__(256) __half g_W1h[256 * 1024];
__device__ __align__(256) __half g_W2h[256 * 1024];
__device__ __align__(256) __half g_W3h[256 * 512];

// ---------------------------------------------------------------------------
// Generic-PTX helpers (compute_103 virtual arch: no tcgen05/'a' features)
// ---------------------------------------------------------------------------
__device__ __forceinline__ uint32_t smem_u32(const void* p) {
    uint32_t a;
    asm("{ .reg .u64 t; cvta.to.shared.u64 t, %1; cvt.u32.u64 %0, t; }"
        : "=r"(a) : "l"(p));
    return a;
}
__device__ __forceinline__ void ldm4(uint32_t* r, uint32_t addr) {
    asm volatile(
        "ldmatrix.sync.aligned.m8n8.x4.shared.b16 {%0,%1,%2,%3}, [%4];"
        : "=r"(r[0]), "=r"(r[1]), "=r"(r[2]), "=r"(r[3]) : "r"(addr));
}
__device__ __forceinline__ void mma_f16(float* c, const uint32_t* a,
                                        uint32_t b0, uint32_t b1) {
    asm volatile(
        "mma.sync.aligned.m16n8k16.row.col.f32.f16.f16.f32 "
        "{%0,%1,%2,%3}, {%4,%5,%6,%7}, {%8,%9}, {%0,%1,%2,%3};"
        : "+f"(c[0]), "+f"(c[1]), "+f"(c[2]), "+f"(c[3])
        : "r"(a[0]), "r"(a[1]), "r"(a[2]), "r"(a[3]), "r"(b0), "r"(b1));
}
__device__ __forceinline__ void cp16(uint32_t dst, const void* src) {
    asm volatile("cp.async.ca.shared.global [%0], [%1], 16;"
                 :: "r"(dst), "l"(src) : "memory");
}
__device__ __forceinline__ void cp16cg(uint32_t dst, const void* src) {
    asm volatile("cp.async.cg.shared.global [%0], [%1], 16;"
                 :: "r"(dst), "l"(src) : "memory");
}
#define CP_COMMIT() asm volatile("cp.async.commit_group;" ::: "memory")
template <int N>
__device__ __forceinline__ void cp_wait() {
    asm volatile("cp.async.wait_group %0;" :: "n"(N) : "memory");
}

#define HSTR 40   // linear kernel SMEM row stride (halfs)
#define JSTR 72   // bilinear SMEM row stride (halfs): 64 data + 8 pad
#define ABLK (128 * JSTR)   // one SMEM slot (halfs)

// ---------------------------------------------------------------------------
// fp32 -> fp16 bulk convert
// ---------------------------------------------------------------------------
__global__ void f2h_kernel(const float* __restrict__ src,
                           __half* __restrict__ dst, int n) {
    int i = (blockIdx.x * blockDim.x + threadIdx.x) * 4;
    int stride = gridDim.x * blockDim.x * 4;
    for (; i < n; i += stride) {
        float4 v = *(const float4*)(src + i);
        ((__half2*)(dst + i))[0] = __floats2half2_rn(v.x, v.y);
        ((__half2*)(dst + i))[1] = __floats2half2_rn(v.z, v.w);
    }
}

// ---------------------------------------------------------------------------
// phrase embedding (fp16 output)
// ---------------------------------------------------------------------------
__global__ void embed_kernel(const int* __restrict__ ids,
                             const float* __restrict__ w,
                             const float* __restrict__ emb,
                             __half* __restrict__ outh) {
    int b = blockIdx.x;
    int t = threadIdx.x;
    const float4* emb4 = (const float4*)emb;
    float4 acc = make_float4(0.f, 0.f, 0.f, 0.f);
#pragma unroll
    for (int n = 0; n < N_SZ; n++) {
        int   id = __ldg(&ids[b * N_SZ + n]);
        float wn = __ldg(&w[b * N_SZ + n]);
        float4 e = __ldg(&emb4[(size_t)id * 128 + t]);
        acc.x = fmaf(wn, e.x, acc.x);
        acc.y = fmaf(wn, e.y, acc.y);
        acc.z = fmaf(wn, e.z, acc.z);
        acc.w = fmaf(wn, e.w, acc.w);
    }
    ((__half2*)outh)[(size_t)b * 256 + t * 2]     = __floats2half2_rn(acc.x, acc.y);
    ((__half2*)outh)[(size_t)b * 256 + t * 2 + 1] = __floats2half2_rn(acc.z, acc.w);
}

// ---------------------------------------------------------------------------
// finish: v = tanh(Y + L); OUT = v (fp32), OUTh = v (fp16)
// ---------------------------------------------------------------------------
__global__ void finish_kernel(const float* __restrict__ Y,
                              const float* __restrict__ L,
                              float* __restrict__ OUT,
                              __half* __restrict__ OUTh) {
    int i = blockIdx.x * 256 + threadIdx.x;
    float v = tanhf(Y[i] + L[i]);
    OUT[i] = v;
    OUTh[i] = __float2half(v);
}

// ---------------------------------------------------------------------------
// linear term via fp16 mma (unchanged)
// ---------------------------------------------------------------------------
__global__ void __launch_bounds__(256, 2)
linear_f16(const __half* __restrict__ X1h, const __half* __restrict__ X2h,
           const __half* __restrict__ Wh, const float* __restrict__ bias,
           float* __restrict__ L, int Dh) {
    __shared__ __align__(16) __half Abuf[2][64 * HSTR];
    __shared__ __align__(16) __half Bbuf[2][128 * HSTR];

    const int tid = threadIdx.x, lane = tid & 31, w = tid >> 5;
    const int wm = w >> 2, wn = w & 3;
    const int b0 = blockIdx.x * 64, k0 = blockIdx.y * 128;
    const int g = lane >> 3, lr = lane & 7;
    const int a_row = (g & 1) * 8 + lr, a_col = (g >> 1) * 8;
    const int b_row = (g >> 1) * 8 + lr, b_col = (g & 1) * 8;

    uint32_t a_addr[2], b_addr[2];
#pragma unroll
    for (int buf = 0; buf < 2; buf++) {
        a_addr[buf] = smem_u32(&Abuf[buf][(wm * 32 + a_row) * HSTR + a_col]);
        b_addr[buf] = smem_u32(&Bbuf[buf][(wn * 32 + b_row) * HSTR + b_col]);
    }

    float acc[2][4][4];
#pragma unroll
    for (int mt = 0; mt < 2; mt++)
#pragma unroll
        for (int nt = 0; nt < 4; nt++)
#pragma unroll
            for (int q = 0; q < 4; q++) acc[mt][nt][q] = 0.f;

    const int HC = Dh / 32;
    const int NC = 2 * HC;
    const int srow = tid >> 2, sseg = (tid & 3) * 8;

    auto stage = [&](int c, int nb) {
        const __half* Asrc = (c < HC) ? X1h : X2h;
        int dof = ((c < HC) ? c : c - HC) * 32;
        cp16(smem_u32(&Abuf[nb][srow * HSTR + sseg]),
             Asrc + (size_t)(b0 + srow) * Dh + dof + sseg);
        cp16(smem_u32(&Bbuf[nb][srow * HSTR + sseg]),
             Wh + (size_t)(k0 + srow) * (2 * Dh) + c * 32 + sseg);
        cp16(smem_u32(&Bbuf[nb][(srow + 64) * HSTR + sseg]),
             Wh + (size_t)(k0 + srow + 64) * (2 * Dh) + c * 32 + sseg);
    };

    stage(0, 0);
    CP_COMMIT();
    for (int c = 0; c < NC; c++) {
        if (c + 1 < NC) {
            stage(c + 1, (c + 1) & 1);
            CP_COMMIT();
            cp_wait<1>();
        } else {
            cp_wait<0>();
        }
        __syncthreads();
        int buf = c & 1;
#pragma unroll
        for (int ks = 0; ks < 2; ks++) {
            uint32_t a[2][4];
            ldm4(a[0], a_addr[buf] + (0 * 16 * HSTR + ks * 16) * 2);
            ldm4(a[1], a_addr[buf] + (1 * 16 * HSTR + ks * 16) * 2);
            uint32_t br[2][4];
            ldm4(br[0], b_addr[buf] + (ks * 16) * 2);
            ldm4(br[1], b_addr[buf] + (16 * HSTR + ks * 16) * 2);
#pragma unroll
            for (int mt = 0; mt < 2; mt++)
#pragma unroll
                for (int nt = 0; nt < 4; nt++) {
                    const uint32_t* bb = br[nt >> 1];
                    mma_f16(acc[mt][nt], a[mt], bb[(nt & 1) * 2],
                            bb[(nt & 1) * 2 + 1]);
                }
        }
        __syncthreads();
    }

    const int er = lane >> 2, ec = lane & 3;
#pragma unroll
    for (int mt = 0; mt < 2; mt++) {
        int r = b0 + wm * 32 + mt * 16 + er;
#pragma unroll
        for (int nt = 0; nt < 4; nt++) {
            int kk = k0 + wn * 32 + nt * 8 + ec * 2;
            float bz0 = __ldg(&bias[kk]), bz1 = __ldg(&bias[kk + 1]);
            L[(size_t)r * K_SZ + kk]           = acc[mt][nt][0] + bz0;
            L[(size_t)r * K_SZ + kk + 1]       = acc[mt][nt][1] + bz1;
            L[(size_t)(r + 8) * K_SZ + kk]     = acc[mt][nt][2] + bz0;
            L[(size_t)(r + 8) * K_SZ + kk + 1] = acc[mt][nt][3] + bz1;
        }
    }
}

// ---------------------------------------------------------------------------
// bilinear v7: j-OUTER / i-INNER with A (X2) fragments register-resident
// across the i-chunks of a j-chunk (A LDSM cut 4x). Fold is linear, so acc
// is zeroed and folded PER UNIT. X2 staged once per j-chunk (double-buffered
// SMEM); T streamed through a ring-3 with ONE __syncthreads per unit.
// 256 thr, 8 warps 2m x 4n, warp tile m64 x n32, BT=128, 1 CTA/SM.
// SMEM slots: X2 [0..2)*ABLK, T ring [2..5)*ABLK.
// ---------------------------------------------------------------------------
template <int DI, int DJ>
__global__ void __launch_bounds__(256, 1)
bilinear_v7(const __half* __restrict__ Th, const __half* __restrict__ X1h,
            const __half* __restrict__ X2h, float* __restrict__ Y) {
    extern __shared__ __align__(16) __half sm[];
    float* ysum = (float*)(sm + 5 * ABLK);

    const int tid = threadIdx.x, lane = tid & 31, w = tid >> 5;
    const int wm = w >> 2, wn = w & 3;       // 2 x 4
    const int b0 = blockIdx.x * 128, k = blockIdx.y;
    const __half* Tk = Th + (size_t)k * DI * DJ;

    if (tid < 128) ysum[tid] = 0.f;

    const int g = lane >> 3, lr = lane & 7;
    const int a_row = (g & 1) * 8 + lr, a_col = (g >> 1) * 8;
    const int b_row = (g >> 1) * 8 + lr, b_col = (g & 1) * 8;

    uint32_t xa_addr[2], tb_addr[3];
#pragma unroll
    for (int s = 0; s < 2; s++)
        xa_addr[s] = smem_u32(&sm[s * ABLK + (wm * 64 + a_row) * JSTR + a_col]);
#pragma unroll
    for (int s = 0; s < 3; s++)
        tb_addr[s] = smem_u32(&sm[(2 + s) * ABLK + (wn * 32 + b_row) * JSTR + b_col]);

    const int er = lane >> 2, ec = lane & 3;

    float y[2][4];
#pragma unroll
    for (int i = 0; i < 2; i++)
#pragma unroll
        for (int m = 0; m < 4; m++) y[i][m] = 0.f;

    constexpr int NICH = DI / 128;
    constexpr int JCH = DJ / 64;
    constexpr int UNITS = NICH * JCH;

    uint32_t aF[4][4][4];   // A fragments [mt][ks][4] — register-resident per jc
    float acc[4][4][4];

    // staging lambdas: each thread moves 4 x 16B segs per 128x64 tile
    auto stageT = [&](int u, int slot) {
        const int jc = u / NICH, ich = u % NICH;
        const uint32_t bo = (2 + slot) * ABLK;
        const __half* src = Tk + (size_t)(ich * 128) * DJ + jc * 64;
#pragma unroll
        for (int s = 0; s < 4; s++) {
            int t = tid + s * 256;
            int row = t >> 3, seg = (t & 7) * 8;
            cp16cg(smem_u32(&sm[bo + row * JSTR + seg]),
                   src + (size_t)row * DJ + seg);
        }
    };
    auto stageX = [&](int jc, int slot) {
        const uint32_t ao = slot * ABLK;
        const __half* src = X2h + jc * 64;
#pragma unroll
        for (int s = 0; s < 4; s++) {
            int t = tid + s * 256;
            int row = t >> 3, seg = (t & 7) * 8;
            cp16cg(smem_u32(&sm[ao + row * JSTR + seg]),
                   src + (size_t)(b0 + row) * DJ + seg);
        }
    };

    int s_cur = 0, s_nxt = 1;
    stageX(0, 0);
    stageT(0, 0);
    CP_COMMIT();

    for (int u = 0; u < UNITS; u++) {
        const int jc = u / NICH, ich = u % NICH;
        if (u + 1 < UNITS) {
            stageT(u + 1, s_nxt);
            if ((u + 1) % NICH == 0)               // next unit starts a new jc
                stageX((u + 1) / NICH, (((u + 1) / NICH) & 1));
            CP_COMMIT();
            cp_wait<1>();
        } else {
            cp_wait<0>();
        }
        __syncthreads();  // single barrier per unit (ring-3 + X2-double safe)

        if (ich == 0) {
            // load A fragments for this j-chunk ONCE (reused by all i-chunks)
            const uint32_t xa = xa_addr[jc & 1];
#pragma unroll
            for (int mt = 0; mt < 4; mt++)
#pragma unroll
                for (int ks = 0; ks < 4; ks++)
                    ldm4(aF[mt][ks], xa + (mt * 16 * JSTR + ks * 16) * 2);
        }

#pragma unroll
        for (int mt = 0; mt < 4; mt++)
#pragma unroll
            for (int nt = 0; nt < 4; nt++)
#pragma unroll
                for (int q = 0; q < 4; q++) acc[mt][nt][q] = 0.f;

        // B fragments: software-pipelined across the 4 k-steps
        const uint32_t ba = tb_addr[s_cur];
        uint32_t brA[2][4], brB[2][4];
        ldm4(brA[0], ba);
        ldm4(brA[1], ba + (16 * JSTR) * 2);
#pragma unroll
        for (int ks = 0; ks < 4; ks++) {
            uint32_t (*cur)[4] = (ks & 1) ? brB : brA;
            uint32_t (*nxt)[4] = (ks & 1) ? brA : brB;
            if (ks < 3) {
                ldm4(nxt[0], ba + ((ks + 1) * 16) * 2);
                ldm4(nxt[1], ba + (16 * JSTR + (ks + 1) * 16) * 2);
            }
#pragma unroll
            for (int mt = 0; mt < 4; mt++)
#pragma unroll
                for (int nt = 0; nt < 4; nt++) {
                    const uint32_t* bb = cur[nt >> 1];
                    mma_f16(acc[mt][nt], aF[mt][ks], bb[(nt & 1) * 2],
                            bb[(nt & 1) * 2 + 1]);
                }
        }

        // fold this unit's partial C into y with X1 (linearity of the fold)
#pragma unroll
        for (int mt = 0; mt < 4; mt++) {
            int r = wm * 64 + mt * 16 + er;
#pragma unroll
            for (int nt = 0; nt < 4; nt++) {
                int ii = ich * 128 + wn * 32 + nt * 8 + ec * 2;
                __half2 xa = *(const __half2*)&X1h[(size_t)(b0 + r) * DI + ii];
                __half2 xb = *(const __half2*)&X1h[(size_t)(b0 + r + 8) * DI + ii];
                float2 fa = __half22float2(xa);
                float2 fb = __half22float2(xb);
                y[0][mt] = fmaf(acc[mt][nt][0], fa.x, y[0][mt]);
                y[0][mt] = fmaf(acc[mt][nt][1], fa.y, y[0][mt]);
                y[1][mt] = fmaf(acc[mt][nt][2], fb.x, y[1][mt]);
                y[1][mt] = fmaf(acc[mt][nt][3], fb.y, y[1][mt]);
            }
        }

        s_cur = s_nxt;
        if (++s_nxt == 3) s_nxt = 0;
    }

    // reduce over 4 column-quad lanes; combine 4 n-warps via smem atomics
#pragma unroll
    for (int i = 0; i < 2; i++)
#pragma unroll
        for (int mt = 0; mt < 4; mt++) {
            y[i][mt] += __shfl_xor_sync(0xffffffffu, y[i][mt], 1);
            y[i][mt] += __shfl_xor_sync(0xffffffffu, y[i][mt], 2);
        }
    if (ec == 0) {
#pragma unroll
        for (int mt = 0; mt < 4; mt++) {
            atomicAdd(&ysum[wm * 64 + mt * 16 + er], y[0][mt]);
            atomicAdd(&ysum[wm * 64 + mt * 16 + er + 8], y[1][mt]);
        }
    }
    __syncthreads();
    if (tid < 128) {
        size_t b = (size_t)b0 + tid;
        Y[b * K_SZ + k] = ysum[tid];
    }
}

// ---------------------------------------------------------------------------
// Launch — ordered so the 4th launch (observed ncu capture slot) is bilinear1.
// ---------------------------------------------------------------------------
extern "C" void kernel_launch(void* const* d_in, const int* in_sizes, int n_in,
                              void* d_out, int out_size) {
    const int*   subj_id = (const int*)d_in[0];
    const float* subj_w  = (const float*)d_in[1];
    const int*   verb_id = (const int*)d_in[2];
    const float* verb_w  = (const float*)d_in[3];
    const int*   obj_id  = (const int*)d_in[4];
    const float* obj_w   = (const float*)d_in[5];
    const float* emb     = (const float*)d_in[6];
    const float* t1      = (const float*)d_in[7];
    const float* t2      = (const float*)d_in[8];
    const float* t3      = (const float*)d_in[9];
    const float* W1      = (const float*)d_in[10];
    const float* b1      = (const float*)d_in[11];
    const float* W2      = (const float*)d_in[12];
    const float* b2      = (const float*)d_in[13];
    const float* W3      = (const float*)d_in[14];
    const float* b3      = (const float*)d_in[15];
    float* out = (float*)d_out;

    float *pL1, *pL2, *pL3, *pY, *pR1, *pR2;
    __half *pSh, *pVh, *pOh, *pR1h, *pR2h;
    __half *pT1h, *pT2h, *pT3h, *pW1h, *pW2h, *pW3h;
    cudaGetSymbolAddress((void**)&pL1,  g_L1);
    cudaGetSymbolAddress((void**)&pL2,  g_L2);
    cudaGetSymbolAddress((void**)&pL3,  g_L3);
    cudaGetSymbolAddress((void**)&pY,   g_Y);
    cudaGetSymbolAddress((void**)&pR1,  g_R1);
    cudaGetSymbolAddress((void**)&pR2,  g_R2);
    cudaGetSymbolAddress((void**)&pSh,  g_Sh);
    cudaGetSymbolAddress((void**)&pVh,  g_Vh);
    cudaGetSymbolAddress((void**)&pOh,  g_Oh);
    cudaGetSymbolAddress((void**)&pR1h, g_R1h);
    cudaGetSymbolAddress((void**)&pR2h, g_R2h);
    cudaGetSymbolAddress((void**)&pT1h, g_T1h);
    cudaGetSymbolAddress((void**)&pT2h, g_T2h);
    cudaGetSymbolAddress((void**)&pT3h, g_T3h);
    cudaGetSymbolAddress((void**)&pW1h, g_W1h);
    cudaGetSymbolAddress((void**)&pW2h, g_W2h);
    cudaGetSymbolAddress((void**)&pW3h, g_W3h);

    const int smem_v7 = 5 * ABLK * 2 + 128 * 4;  // 92672 B
    cudaFuncSetAttribute(bilinear_v7<512, 512>,
                         cudaFuncAttributeMaxDynamicSharedMemorySize, smem_v7);
    cudaFuncSetAttribute(bilinear_v7<256, 256>,
                         cudaFuncAttributeMaxDynamicSharedMemorySize, smem_v7);

    dim3 lin_grid(B_SZ / 64, K_SZ / 128);
    dim3 bil_grid(B_SZ / 128, K_SZ);
    dim3 fin_grid(B_SZ * K_SZ / 256);

    // phase 1 — bilinear1 is launch #4 (ncu capture slot)
    embed_kernel<<<B_SZ, 128>>>(subj_id, subj_w, emb, pSh);           // 1
    embed_kernel<<<B_SZ, 128>>>(verb_id, verb_w, emb, pVh);           // 2
    f2h_kernel<<<4096, 256>>>(t1, pT1h, 256 * 512 * 512);             // 3
    bilinear_v7<512, 512><<<bil_grid, 256, smem_v7>>>(pT1h, pSh, pVh, pY);  // 4 *
    f2h_kernel<<<256, 256>>>(W1, pW1h, 256 * 1024);                   // 5
    linear_f16<<<lin_grid, 256>>>(pSh, pVh, pW1h, b1, pL1, 512);      // 6
    finish_kernel<<<fin_grid, 256>>>(pY, pL1, pR1, pR1h);             // 7

    // phase 2
    embed_kernel<<<B_SZ, 128>>>(obj_id, obj_w, emb, pOh);
    f2h_kernel<<<4096, 256>>>(t2, pT2h, 256 * 512 * 512);
    bilinear_v7<512, 512><<<bil_grid, 256, smem_v7>>>(pT2h, pVh, pOh, pY);
    f2h_kernel<<<256, 256>>>(W2, pW2h, 256 * 1024);
    linear_f16<<<lin_grid, 256>>>(pVh, pOh, pW2h, b2, pL2, 512);
    finish_kernel<<<fin_grid, 256>>>(pY, pL2, pR2, pR2h);

    // phase 3
    f2h_kernel<<<256, 256>>>(W3, pW3h, 256 * 512);
    linear_f16<<<lin_grid, 256>>>(pR1h, pR2h, pW3h, b3, pL3, 256);
    f2h_kernel<<<2048, 256>>>(t3, pT3h, 256 * 256 * 256);
    bilinear_v7<256, 256><<<bil_grid, 256, smem_v7>>>(pT3h, pR1h, pR2h, pY);
    finish_kernel<<<fin_grid, 256>>>(pY, pL3, out, pOh);
}

// round 14
// speedup vs baseline: 2.3318x; 2.3318x over previous
#include <cuda_runtime.h>
#include <cuda_fp16.h>
#include <math.h>
#include <stdint.h>

#define B_SZ 4096
#define K_SZ 256
#define N_SZ 8

// ---------------------------------------------------------------------------
// Scratch (device globals; allocations are banned)
// ---------------------------------------------------------------------------
__device__ __align__(256) float  g_L1[B_SZ * 256];
__device__ __align__(256) float  g_L2[B_SZ * 256];
__device__ __align__(256) float  g_L3[B_SZ * 256];
__device__ __align__(256) float  g_Y[B_SZ * 256];    // raw bilinear output
__device__ __align__(256) float  g_R1[B_SZ * 256];
__device__ __align__(256) float  g_R2[B_SZ * 256];
__device__ __align__(256) __half g_Sh[B_SZ * 512];
__device__ __align__(256) __half g_Vh[B_SZ * 512];
__device__ __align__(256) __half g_Oh[B_SZ * 512];   // also phase-3 OUTh dump
__device__ __align__(256) __half g_R1h[B_SZ * 256];
__device__ __align__(256) __half g_R2h[B_SZ * 256];
__device__ __align__(256) __half g_T1h[256u * 512u * 512u];
__device__ __align__(256) __half g_T2h[256u * 512u * 512u];
__device__ __align__(256) __half g_T3h[256u * 256u * 256u];
__device__ __align__(256) __half g_W1h[256 * 1024];
__device__ __align__(256) __half g_W2h[256 * 1024];
__device__ __align__(256) __half g_W3h[256 * 512];

// ---------------------------------------------------------------------------
// Generic-PTX helpers (compute_103 virtual arch: no tcgen05/'a' features)
// ---------------------------------------------------------------------------
__device__ __forceinline__ uint32_t smem_u32(const void* p) {
    uint32_t a;
    asm("{ .reg .u64 t; cvta.to.shared.u64 t, %1; cvt.u32.u64 %0, t; }"
        : "=r"(a) : "l"(p));
    return a;
}
__device__ __forceinline__ void ldm4(uint32_t* r, uint32_t addr) {
    asm volatile(
        "ldmatrix.sync.aligned.m8n8.x4.shared.b16 {%0,%1,%2,%3}, [%4];"
        : "=r"(r[0]), "=r"(r[1]), "=r"(r[2]), "=r"(r[3]) : "r"(addr));
}
__device__ __forceinline__ void mma_f16(float* c, const uint32_t* a,
                                        uint32_t b0, uint32_t b1) {
    asm volatile(
        "mma.sync.aligned.m16n8k16.row.col.f32.f16.f16.f32 "
        "{%0,%1,%2,%3}, {%4,%5,%6,%7}, {%8,%9}, {%0,%1,%2,%3};"
        : "+f"(c[0]), "+f"(c[1]), "+f"(c[2]), "+f"(c[3])
        : "r"(a[0]), "r"(a[1]), "r"(a[2]), "r"(a[3]), "r"(b0), "r"(b1));
}
__device__ __forceinline__ void cp16(uint32_t dst, const void* src) {
    asm volatile("cp.async.ca.shared.global [%0], [%1], 16;"
                 :: "r"(dst), "l"(src) : "memory");
}
__device__ __forceinline__ void cp16cg(uint32_t dst, const void* src) {
    asm volatile("cp.async.cg.shared.global [%0], [%1], 16;"
                 :: "r"(dst), "l"(src) : "memory");
}
#define CP_COMMIT() asm volatile("cp.async.commit_group;" ::: "memory")
template <int N>
__device__ __forceinline__ void cp_wait() {
    asm volatile("cp.async.wait_group %0;" :: "n"(N) : "memory");
}

#define HSTR 40   // linear kernel SMEM row stride (halfs)
#define JSTR 72   // bilinear SMEM row stride (halfs): 64 data + 8 pad
#define ABLK (128 * JSTR)   // one ring slot (halfs)

// ---------------------------------------------------------------------------
// fp32 -> fp16 bulk convert
// ---------------------------------------------------------------------------
__global__ void f2h_kernel(const float* __restrict__ src,
                           __half* __restrict__ dst, int n) {
    int i = (blockIdx.x * blockDim.x + threadIdx.x) * 4;
    int stride = gridDim.x * blockDim.x * 4;
    for (; i < n; i += stride) {
        float4 v = *(const float4*)(src + i);
        ((__half2*)(dst + i))[0] = __floats2half2_rn(v.x, v.y);
        ((__half2*)(dst + i))[1] = __floats2half2_rn(v.z, v.w);
    }
}

// ---------------------------------------------------------------------------
// phrase embedding (fp16 output)
// ---------------------------------------------------------------------------
__global__ void embed_kernel(const int* __restrict__ ids,
                             const float* __restrict__ w,
                             const float* __restrict__ emb,
                             __half* __restrict__ outh) {
    int b = blockIdx.x;
    int t = threadIdx.x;
    const float4* emb4 = (const float4*)emb;
    float4 acc = make_float4(0.f, 0.f, 0.f, 0.f);
#pragma unroll
    for (int n = 0; n < N_SZ; n++) {
        int   id = __ldg(&ids[b * N_SZ + n]);
        float wn = __ldg(&w[b * N_SZ + n]);
        float4 e = __ldg(&emb4[(size_t)id * 128 + t]);
        acc.x = fmaf(wn, e.x, acc.x);
        acc.y = fmaf(wn, e.y, acc.y);
        acc.z = fmaf(wn, e.z, acc.z);
        acc.w = fmaf(wn, e.w, acc.w);
    }
    ((__half2*)outh)[(size_t)b * 256 + t * 2]     = __floats2half2_rn(acc.x, acc.y);
    ((__half2*)outh)[(size_t)b * 256 + t * 2 + 1] = __floats2half2_rn(acc.z, acc.w);
}

// ---------------------------------------------------------------------------
// finish: v = tanh(Y + L); OUT = v (fp32), OUTh = v (fp16)
// ---------------------------------------------------------------------------
__global__ void finish_kernel(const float* __restrict__ Y,
                              const float* __restrict__ L,
                              float* __restrict__ OUT,
                              __half* __restrict__ OUTh) {
    int i = blockIdx.x * 256 + threadIdx.x;
    float v = tanhf(Y[i] + L[i]);
    OUT[i] = v;
    OUTh[i] = __float2half(v);
}

// ---------------------------------------------------------------------------
// linear term via fp16 mma (unchanged)
// ---------------------------------------------------------------------------
__global__ void __launch_bounds__(256, 2)
linear_f16(const __half* __restrict__ X1h, const __half* __restrict__ X2h,
           const __half* __restrict__ Wh, const float* __restrict__ bias,
           float* __restrict__ L, int Dh) {
    __shared__ __align__(16) __half Abuf[2][64 * HSTR];
    __shared__ __align__(16) __half Bbuf[2][128 * HSTR];

    const int tid = threadIdx.x, lane = tid & 31, w = tid >> 5;
    const int wm = w >> 2, wn = w & 3;
    const int b0 = blockIdx.x * 64, k0 = blockIdx.y * 128;
    const int g = lane >> 3, lr = lane & 7;
    const int a_row = (g & 1) * 8 + lr, a_col = (g >> 1) * 8;
    const int b_row = (g >> 1) * 8 + lr, b_col = (g & 1) * 8;

    uint32_t a_addr[2], b_addr[2];
#pragma unroll
    for (int buf = 0; buf < 2; buf++) {
        a_addr[buf] = smem_u32(&Abuf[buf][(wm * 32 + a_row) * HSTR + a_col]);
        b_addr[buf] = smem_u32(&Bbuf[buf][(wn * 32 + b_row) * HSTR + b_col]);
    }

    float acc[2][4][4];
#pragma unroll
    for (int mt = 0; mt < 2; mt++)
#pragma unroll
        for (int nt = 0; nt < 4; nt++)
#pragma unroll
            for (int q = 0; q < 4; q++) acc[mt][nt][q] = 0.f;

    const int HC = Dh / 32;
    const int NC = 2 * HC;
    const int srow = tid >> 2, sseg = (tid & 3) * 8;

    auto stage = [&](int c, int nb) {
        const __half* Asrc = (c < HC) ? X1h : X2h;
        int dof = ((c < HC) ? c : c - HC) * 32;
        cp16(smem_u32(&Abuf[nb][srow * HSTR + sseg]),
             Asrc + (size_t)(b0 + srow) * Dh + dof + sseg);
        cp16(smem_u32(&Bbuf[nb][srow * HSTR + sseg]),
             Wh + (size_t)(k0 + srow) * (2 * Dh) + c * 32 + sseg);
        cp16(smem_u32(&Bbuf[nb][(srow + 64) * HSTR + sseg]),
             Wh + (size_t)(k0 + srow + 64) * (2 * Dh) + c * 32 + sseg);
    };

    stage(0, 0);
    CP_COMMIT();
    for (int c = 0; c < NC; c++) {
        if (c + 1 < NC) {
            stage(c + 1, (c + 1) & 1);
            CP_COMMIT();
            cp_wait<1>();
        } else {
            cp_wait<0>();
        }
        __syncthreads();
        int buf = c & 1;
#pragma unroll
        for (int ks = 0; ks < 2; ks++) {
            uint32_t a[2][4];
            ldm4(a[0], a_addr[buf] + (0 * 16 * HSTR + ks * 16) * 2);
            ldm4(a[1], a_addr[buf] + (1 * 16 * HSTR + ks * 16) * 2);
            uint32_t br[2][4];
            ldm4(br[0], b_addr[buf] + (ks * 16) * 2);
            ldm4(br[1], b_addr[buf] + (16 * HSTR + ks * 16) * 2);
#pragma unroll
            for (int mt = 0; mt < 2; mt++)
#pragma unroll
                for (int nt = 0; nt < 4; nt++) {
                    const uint32_t* bb = br[nt >> 1];
                    mma_f16(acc[mt][nt], a[mt], bb[(nt & 1) * 2],
                            bb[(nt & 1) * 2 + 1]);
                }
        }
        __syncthreads();
    }

    const int er = lane >> 2, ec = lane & 3;
#pragma unroll
    for (int mt = 0; mt < 2; mt++) {
        int r = b0 + wm * 32 + mt * 16 + er;
#pragma unroll
        for (int nt = 0; nt < 4; nt++) {
            int kk = k0 + wn * 32 + nt * 8 + ec * 2;
            float bz0 = __ldg(&bias[kk]), bz1 = __ldg(&bias[kk + 1]);
            L[(size_t)r * K_SZ + kk]           = acc[mt][nt][0] + bz0;
            L[(size_t)r * K_SZ + kk + 1]       = acc[mt][nt][1] + bz1;
            L[(size_t)(r + 8) * K_SZ + kk]     = acc[mt][nt][2] + bz0;
            L[(size_t)(r + 8) * K_SZ + kk + 1] = acc[mt][nt][3] + bz1;
        }
    }
}

// ---------------------------------------------------------------------------
// bilinear v8: R12's v6 (ring-3, ONE barrier/unit, i-outer/j-inner, fold per
// i-chunk) + A-fragment double buffering across the mt loop (LDSM->HMMA
// latency hidden by a full mma quad). Everything else identical to v6.
// 256 thr, 8 warps 2m x 4n, warp tile m64 x n32, BT=128, 2 CTA/SM.
// ---------------------------------------------------------------------------
template <int DI, int DJ>
__global__ void __launch_bounds__(256, 2)
bilinear_v8(const __half* __restrict__ Th, const __half* __restrict__ X1h,
            const __half* __restrict__ X2h, float* __restrict__ Y) {
    extern __shared__ __align__(16) __half sm[];
    // layout: A slots [0..3)*ABLK, B slots [3..6)*ABLK, ysum floats after
    float* ysum = (float*)(sm + 6 * ABLK);

    const int tid = threadIdx.x, lane = tid & 31, w = tid >> 5;
    const int wm = w >> 2, wn = w & 3;       // 2 x 4
    const int b0 = blockIdx.x * 128, k = blockIdx.y;
    const __half* Tk = Th + (size_t)k * DI * DJ;

    if (tid < 128) ysum[tid] = 0.f;

    const int g = lane >> 3, lr = lane & 7;
    const int a_row = (g & 1) * 8 + lr, a_col = (g >> 1) * 8;
    const int b_row = (g >> 1) * 8 + lr, b_col = (g & 1) * 8;

    uint32_t a_addr[3], b_addr[3];
#pragma unroll
    for (int s = 0; s < 3; s++) {
        a_addr[s] = smem_u32(&sm[s * ABLK + (wm * 64 + a_row) * JSTR + a_col]);
        b_addr[s] = smem_u32(&sm[(3 + s) * ABLK + (wn * 32 + b_row) * JSTR + b_col]);
    }

    const int er = lane >> 2, ec = lane & 3;

    float y[2][4];
#pragma unroll
    for (int i = 0; i < 2; i++)
#pragma unroll
        for (int m = 0; m < 4; m++) y[i][m] = 0.f;

    constexpr int UNITS = (DI / 128) * (DJ / 64);
    constexpr int JCH = DJ / 64;
    float acc[4][4][4];

    auto stage = [&](int u, int slot) {
        const int ich = u / JCH, j0 = (u % JCH) * 64;
        const uint32_t ao = slot * ABLK;
        const uint32_t bo = (3 + slot) * ABLK;
#pragma unroll
        for (int s = 0; s < 4; s++) {
            int t = tid + s * 256;
            int row = t >> 3, seg = (t & 7) * 8;
            cp16cg(smem_u32(&sm[ao + row * JSTR + seg]),
                   X2h + (size_t)(b0 + row) * DJ + j0 + seg);
            cp16cg(smem_u32(&sm[bo + row * JSTR + seg]),
                   Tk + (size_t)(ich * 128 + row) * DJ + j0 + seg);
        }
    };

    int s_cur = 0, s_nxt = 1;
    stage(0, 0);
    CP_COMMIT();
    for (int u = 0; u < UNITS; u++) {
        if (u + 1 < UNITS) {
            stage(u + 1, s_nxt);
            CP_COMMIT();
            cp_wait<1>();
        } else {
            cp_wait<0>();
        }
        __syncthreads();  // the ONLY barrier per unit (ring-3 safe)

        const int jc = u % JCH, ich = u / JCH;
        if (jc == 0) {
#pragma unroll
            for (int mt = 0; mt < 4; mt++)
#pragma unroll
                for (int nt = 0; nt < 4; nt++)
#pragma unroll
                    for (int q = 0; q < 4; q++) acc[mt][nt][q] = 0.f;
        }

        const uint32_t aa = a_addr[s_cur], ba = b_addr[s_cur];
        // B fragments pipelined across k-steps; A fragments pipelined across mt
        uint32_t brA[2][4], brB[2][4];
        ldm4(brA[0], ba);
        ldm4(brA[1], ba + (16 * JSTR) * 2);
#pragma unroll
        for (int ks = 0; ks < 4; ks++) {
            uint32_t (*cur)[4] = (ks & 1) ? brB : brA;
            uint32_t (*nxt)[4] = (ks & 1) ? brA : brB;
            if (ks < 3) {
                ldm4(nxt[0], ba + ((ks + 1) * 16) * 2);
                ldm4(nxt[1], ba + (16 * JSTR + (ks + 1) * 16) * 2);
            }
            uint32_t aP[2][4];
            ldm4(aP[0], aa + (ks * 16) * 2);  // mt = 0
#pragma unroll
            for (int mt = 0; mt < 4; mt++) {
                if (mt < 3)
                    ldm4(aP[(mt + 1) & 1],
                         aa + ((mt + 1) * 16 * JSTR + ks * 16) * 2);
                const uint32_t* am = aP[mt & 1];
#pragma unroll
                for (int nt = 0; nt < 4; nt++) {
                    const uint32_t* bb = cur[nt >> 1];
                    mma_f16(acc[mt][nt], am, bb[(nt & 1) * 2],
                            bb[(nt & 1) * 2 + 1]);
                }
            }
        }

        if (jc == JCH - 1) {
#pragma unroll
            for (int mt = 0; mt < 4; mt++) {
                int r = wm * 64 + mt * 16 + er;
#pragma unroll
                for (int nt = 0; nt < 4; nt++) {
                    int ii = ich * 128 + wn * 32 + nt * 8 + ec * 2;
                    __half2 xa = *(const __half2*)&X1h[(size_t)(b0 + r) * DI + ii];
                    __half2 xb = *(const __half2*)&X1h[(size_t)(b0 + r + 8) * DI + ii];
                    float2 fa = __half22float2(xa);
                    float2 fb = __half22float2(xb);
                    y[0][mt] = fmaf(acc[mt][nt][0], fa.x, y[0][mt]);
                    y[0][mt] = fmaf(acc[mt][nt][1], fa.y, y[0][mt]);
                    y[1][mt] = fmaf(acc[mt][nt][2], fb.x, y[1][mt]);
                    y[1][mt] = fmaf(acc[mt][nt][3], fb.y, y[1][mt]);
                }
            }
        }

        s_cur = s_nxt;
        if (++s_nxt == 3) s_nxt = 0;
    }

    // reduce over 4 column-quad lanes; combine 4 n-warps via smem atomics
#pragma unroll
    for (int i = 0; i < 2; i++)
#pragma unroll
        for (int mt = 0; mt < 4; mt++) {
            y[i][mt] += __shfl_xor_sync(0xffffffffu, y[i][mt], 1);
            y[i][mt] += __shfl_xor_sync(0xffffffffu, y[i][mt], 2);
        }
    if (ec == 0) {
#pragma unroll
        for (int mt = 0; mt < 4; mt++) {
            atomicAdd(&ysum[wm * 64 + mt * 16 + er], y[0][mt]);
            atomicAdd(&ysum[wm * 64 + mt * 16 + er + 8], y[1][mt]);
        }
    }
    __syncthreads();
    if (tid < 128) {
        size_t b = (size_t)b0 + tid;
        Y[b * K_SZ + k] = ysum[tid];
    }
}

// ---------------------------------------------------------------------------
// Launch — ordered so the 4th launch (observed ncu capture slot) is bilinear1.
// ---------------------------------------------------------------------------
extern "C" void kernel_launch(void* const* d_in, const int* in_sizes, int n_in,
                              void* d_out, int out_size) {
    const int*   subj_id = (const int*)d_in[0];
    const float* subj_w  = (const float*)d_in[1];
    const int*   verb_id = (const int*)d_in[2];
    const float* verb_w  = (const float*)d_in[3];
    const int*   obj_id  = (const int*)d_in[4];
    const float* obj_w   = (const float*)d_in[5];
    const float* emb     = (const float*)d_in[6];
    const float* t1      = (const float*)d_in[7];
    const float* t2      = (const float*)d_in[8];
    const float* t3      = (const float*)d_in[9];
    const float* W1      = (const float*)d_in[10];
    const float* b1      = (const float*)d_in[11];
    const float* W2      = (const float*)d_in[12];
    const float* b2      = (const float*)d_in[13];
    const float* W3      = (const float*)d_in[14];
    const float* b3      = (const float*)d_in[15];
    float* out = (float*)d_out;

    float *pL1, *pL2, *pL3, *pY, *pR1, *pR2;
    __half *pSh, *pVh, *pOh, *pR1h, *pR2h;
    __half *pT1h, *pT2h, *pT3h, *pW1h, *pW2h, *pW3h;
    cudaGetSymbolAddress((void**)&pL1,  g_L1);
    cudaGetSymbolAddress((void**)&pL2,  g_L2);
    cudaGetSymbolAddress((void**)&pL3,  g_L3);
    cudaGetSymbolAddress((void**)&pY,   g_Y);
    cudaGetSymbolAddress((void**)&pR1,  g_R1);
    cudaGetSymbolAddress((void**)&pR2,  g_R2);
    cudaGetSymbolAddress((void**)&pSh,  g_Sh);
    cudaGetSymbolAddress((void**)&pVh,  g_Vh);
    cudaGetSymbolAddress((void**)&pOh,  g_Oh);
    cudaGetSymbolAddress((void**)&pR1h, g_R1h);
    cudaGetSymbolAddress((void**)&pR2h, g_R2h);
    cudaGetSymbolAddress((void**)&pT1h, g_T1h);
    cudaGetSymbolAddress((void**)&pT2h, g_T2h);
    cudaGetSymbolAddress((void**)&pT3h, g_T3h);
    cudaGetSymbolAddress((void**)&pW1h, g_W1h);
    cudaGetSymbolAddress((void**)&pW2h, g_W2h);
    cudaGetSymbolAddress((void**)&pW3h, g_W3h);

    const int smem_v8 = 6 * ABLK * 2 + 128 * 4;  // 111104 B
    cudaFuncSetAttribute(bilinear_v8<512, 512>,
                         cudaFuncAttributeMaxDynamicSharedMemorySize, smem_v8);
    cudaFuncSetAttribute(bilinear_v8<256, 256>,
                         cudaFuncAttributeMaxDynamicSharedMemorySize, smem_v8);

    dim3 lin_grid(B_SZ / 64, K_SZ / 128);
    dim3 bil_grid(B_SZ / 128, K_SZ);
    dim3 fin_grid(B_SZ * K_SZ / 256);

    // phase 1 — bilinear1 is launch #4 (ncu capture slot)
    embed_kernel<<<B_SZ, 128>>>(subj_id, subj_w, emb, pSh);           // 1
    embed_kernel<<<B_SZ, 128>>>(verb_id, verb_w, emb, pVh);           // 2
    f2h_kernel<<<4096, 256>>>(t1, pT1h, 256 * 512 * 512);             // 3
    bilinear_v8<512, 512><<<bil_grid, 256, smem_v8>>>(pT1h, pSh, pVh, pY);  // 4 *
    f2h_kernel<<<256, 256>>>(W1, pW1h, 256 * 1024);                   // 5
    linear_f16<<<lin_grid, 256>>>(pSh, pVh, pW1h, b1, pL1, 512);      // 6
    finish_kernel<<<fin_grid, 256>>>(pY, pL1, pR1, pR1h);             // 7

    // phase 2
    embed_kernel<<<B_SZ, 128>>>(obj_id, obj_w, emb, pOh);
    f2h_kernel<<<4096, 256>>>(t2, pT2h, 256 * 512 * 512);
    bilinear_v8<512, 512><<<bil_grid, 256, smem_v8>>>(pT2h, pVh, pOh, pY);
    f2h_kernel<<<256, 256>>>(W2, pW2h, 256 * 1024);
    linear_f16<<<lin_grid, 256>>>(pVh, pOh, pW2h, b2, pL2, 512);
    finish_kernel<<<fin_grid, 256>>>(pY, pL2, pR2, pR2h);

    // phase 3
    f2h_kernel<<<256, 256>>>(W3, pW3h, 256 * 512);
    linear_f16<<<lin_grid, 256>>>(pR1h, pR2h, pW3h, b3, pL3, 256);
    f2h_kernel<<<2048, 256>>>(t3, pT3h, 256 * 256 * 256);
    bilinear_v8<256, 256><<<bil_grid, 256, smem_v8>>>(pT3h, pR1h, pR2h, pY);
    finish_kernel<<<fin_grid, 256>>>(pY, pL3, out, pOh);
}

// round 15
// speedup vs baseline: 2.3806x; 1.0210x over previous
#include <cuda_runtime.h>
#include <cuda_fp16.h>
#include <math.h>
#include <stdint.h>

#define B_SZ 4096
#define K_SZ 256
#define N_SZ 8

// ---------------------------------------------------------------------------
// Scratch (device globals; allocations are banned)
// ---------------------------------------------------------------------------
__device__ __align__(256) float  g_L1[B_SZ * 256];
__device__ __align__(256) float  g_L2[B_SZ * 256];
__device__ __align__(256) float  g_L3[B_SZ * 256];
__device__ __align__(256) float  g_Y[B_SZ * 256];    // raw bilinear output
__device__ __align__(256) float  g_R1[B_SZ * 256];
__device__ __align__(256) float  g_R2[B_SZ * 256];
__device__ __align__(256) __half g_Sh[B_SZ * 512];
__device__ __align__(256) __half g_Vh[B_SZ * 512];
__device__ __align__(256) __half g_Oh[B_SZ * 512];   // also phase-3 OUTh dump
__device__ __align__(256) __half g_R1h[B_SZ * 256];
__device__ __align__(256) __half g_R2h[B_SZ * 256];
__device__ __align__(256) __half g_T1h[256u * 512u * 512u];
__device__ __align__(256) __half g_T2h[256u * 512u * 512u];
__device__ __align__(256) __half g_T3h[256u * 256u * 256u];
__device__ __align__(256) __half g_W1h[256 * 1024];
__device__ __align__(256) __half g_W2h[256 * 1024];
__device__ __align__(256) __half g_W3h[256 * 512];

// ---------------------------------------------------------------------------
// Generic-PTX helpers (compute_103 virtual arch: no tcgen05/'a' features)
// ---------------------------------------------------------------------------
__device__ __forceinline__ uint32_t smem_u32(const void* p) {
    uint32_t a;
    asm("{ .reg .u64 t; cvta.to.shared.u64 t, %1; cvt.u32.u64 %0, t; }"
        : "=r"(a) : "l"(p));
    return a;
}
__device__ __forceinline__ void ldm4(uint32_t* r, uint32_t addr) {
    asm volatile(
        "ldmatrix.sync.aligned.m8n8.x4.shared.b16 {%0,%1,%2,%3}, [%4];"
        : "=r"(r[0]), "=r"(r[1]), "=r"(r[2]), "=r"(r[3]) : "r"(addr));
}
__device__ __forceinline__ void mma_f16(float* c, const uint32_t* a,
                                        uint32_t b0, uint32_t b1) {
    asm volatile(
        "mma.sync.aligned.m16n8k16.row.col.f32.f16.f16.f32 "
        "{%0,%1,%2,%3}, {%4,%5,%6,%7}, {%8,%9}, {%0,%1,%2,%3};"
        : "+f"(c[0]), "+f"(c[1]), "+f"(c[2]), "+f"(c[3])
        : "r"(a[0]), "r"(a[1]), "r"(a[2]), "r"(a[3]), "r"(b0), "r"(b1));
}
__device__ __forceinline__ void cp16(uint32_t dst, const void* src) {
    asm volatile("cp.async.ca.shared.global [%0], [%1], 16;"
                 :: "r"(dst), "l"(src) : "memory");
}
__device__ __forceinline__ void cp16cg(uint32_t dst, const void* src) {
    asm volatile("cp.async.cg.shared.global [%0], [%1], 16;"
                 :: "r"(dst), "l"(src) : "memory");
}
#define CP_COMMIT() asm volatile("cp.async.commit_group;" ::: "memory")
template <int N>
__device__ __forceinline__ void cp_wait() {
    asm volatile("cp.async.wait_group %0;" :: "n"(N) : "memory");
}

#define HSTR 40   // linear kernel SMEM row stride (halfs)
#define JSTR 72   // bilinear SMEM row stride (halfs): 64 data + 8 pad
#define ABLK (128 * JSTR)   // one ring slot (halfs)

// ---------------------------------------------------------------------------
// fp32 -> fp16 bulk convert
// ---------------------------------------------------------------------------
__global__ void f2h_kernel(const float* __restrict__ src,
                           __half* __restrict__ dst, int n) {
    int i = (blockIdx.x * blockDim.x + threadIdx.x) * 4;
    int stride = gridDim.x * blockDim.x * 4;
    for (; i < n; i += stride) {
        float4 v = *(const float4*)(src + i);
        ((__half2*)(dst + i))[0] = __floats2half2_rn(v.x, v.y);
        ((__half2*)(dst + i))[1] = __floats2half2_rn(v.z, v.w);
    }
}

// ---------------------------------------------------------------------------
// phrase embedding (fp16 output)
// ---------------------------------------------------------------------------
__global__ void embed_kernel(const int* __restrict__ ids,
                             const float* __restrict__ w,
                             const float* __restrict__ emb,
                             __half* __restrict__ outh) {
    int b = blockIdx.x;
    int t = threadIdx.x;
    const float4* emb4 = (const float4*)emb;
    float4 acc = make_float4(0.f, 0.f, 0.f, 0.f);
#pragma unroll
    for (int n = 0; n < N_SZ; n++) {
        int   id = __ldg(&ids[b * N_SZ + n]);
        float wn = __ldg(&w[b * N_SZ + n]);
        float4 e = __ldg(&emb4[(size_t)id * 128 + t]);
        acc.x = fmaf(wn, e.x, acc.x);
        acc.y = fmaf(wn, e.y, acc.y);
        acc.z = fmaf(wn, e.z, acc.z);
        acc.w = fmaf(wn, e.w, acc.w);
    }
    ((__half2*)outh)[(size_t)b * 256 + t * 2]     = __floats2half2_rn(acc.x, acc.y);
    ((__half2*)outh)[(size_t)b * 256 + t * 2 + 1] = __floats2half2_rn(acc.z, acc.w);
}

// ---------------------------------------------------------------------------
// finish: v = tanh(Y + L); OUT = v (fp32), OUTh = v (fp16)
// ---------------------------------------------------------------------------
__global__ void finish_kernel(const float* __restrict__ Y,
                              const float* __restrict__ L,
                              float* __restrict__ OUT,
                              __half* __restrict__ OUTh) {
    int i = blockIdx.x * 256 + threadIdx.x;
    float v = tanhf(Y[i] + L[i]);
    OUT[i] = v;
    OUTh[i] = __float2half(v);
}

// ---------------------------------------------------------------------------
// linear term via fp16 mma (unchanged)
// ---------------------------------------------------------------------------
__global__ void __launch_bounds__(256, 2)
linear_f16(const __half* __restrict__ X1h, const __half* __restrict__ X2h,
           const __half* __restrict__ Wh, const float* __restrict__ bias,
           float* __restrict__ L, int Dh) {
    __shared__ __align__(16) __half Abuf[2][64 * HSTR];
    __shared__ __align__(16) __half Bbuf[2][128 * HSTR];

    const int tid = threadIdx.x, lane = tid & 31, w = tid >> 5;
    const int wm = w >> 2, wn = w & 3;
    const int b0 = blockIdx.x * 64, k0 = blockIdx.y * 128;
    const int g = lane >> 3, lr = lane & 7;
    const int a_row = (g & 1) * 8 + lr, a_col = (g >> 1) * 8;
    const int b_row = (g >> 1) * 8 + lr, b_col = (g & 1) * 8;

    uint32_t a_addr[2], b_addr[2];
#pragma unroll
    for (int buf = 0; buf < 2; buf++) {
        a_addr[buf] = smem_u32(&Abuf[buf][(wm * 32 + a_row) * HSTR + a_col]);
        b_addr[buf] = smem_u32(&Bbuf[buf][(wn * 32 + b_row) * HSTR + b_col]);
    }

    float acc[2][4][4];
#pragma unroll
    for (int mt = 0; mt < 2; mt++)
#pragma unroll
        for (int nt = 0; nt < 4; nt++)
#pragma unroll
            for (int q = 0; q < 4; q++) acc[mt][nt][q] = 0.f;

    const int HC = Dh / 32;
    const int NC = 2 * HC;
    const int srow = tid >> 2, sseg = (tid & 3) * 8;

    auto stage = [&](int c, int nb) {
        const __half* Asrc = (c < HC) ? X1h : X2h;
        int dof = ((c < HC) ? c : c - HC) * 32;
        cp16(smem_u32(&Abuf[nb][srow * HSTR + sseg]),
             Asrc + (size_t)(b0 + srow) * Dh + dof + sseg);
        cp16(smem_u32(&Bbuf[nb][srow * HSTR + sseg]),
             Wh + (size_t)(k0 + srow) * (2 * Dh) + c * 32 + sseg);
        cp16(smem_u32(&Bbuf[nb][(srow + 64) * HSTR + sseg]),
             Wh + (size_t)(k0 + srow + 64) * (2 * Dh) + c * 32 + sseg);
    };

    stage(0, 0);
    CP_COMMIT();
    for (int c = 0; c < NC; c++) {
        if (c + 1 < NC) {
            stage(c + 1, (c + 1) & 1);
            CP_COMMIT();
            cp_wait<1>();
        } else {
            cp_wait<0>();
        }
        __syncthreads();
        int buf = c & 1;
#pragma unroll
        for (int ks = 0; ks < 2; ks++) {
            uint32_t a[2][4];
            ldm4(a[0], a_addr[buf] + (0 * 16 * HSTR + ks * 16) * 2);
            ldm4(a[1], a_addr[buf] + (1 * 16 * HSTR + ks * 16) * 2);
            uint32_t br[2][4];
            ldm4(br[0], b_addr[buf] + (ks * 16) * 2);
            ldm4(br[1], b_addr[buf] + (16 * HSTR + ks * 16) * 2);
#pragma unroll
            for (int mt = 0; mt < 2; mt++)
#pragma unroll
                for (int nt = 0; nt < 4; nt++) {
                    const uint32_t* bb = br[nt >> 1];
                    mma_f16(acc[mt][nt], a[mt], bb[(nt & 1) * 2],
                            bb[(nt & 1) * 2 + 1]);
                }
        }
        __syncthreads();
    }

    const int er = lane >> 2, ec = lane & 3;
#pragma unroll
    for (int mt = 0; mt < 2; mt++) {
        int r = b0 + wm * 32 + mt * 16 + er;
#pragma unroll
        for (int nt = 0; nt < 4; nt++) {
            int kk = k0 + wn * 32 + nt * 8 + ec * 2;
            float bz0 = __ldg(&bias[kk]), bz1 = __ldg(&bias[kk + 1]);
            L[(size_t)r * K_SZ + kk]           = acc[mt][nt][0] + bz0;
            L[(size_t)r * K_SZ + kk + 1]       = acc[mt][nt][1] + bz1;
            L[(size_t)(r + 8) * K_SZ + kk]     = acc[mt][nt][2] + bz0;
            L[(size_t)(r + 8) * K_SZ + kk + 1] = acc[mt][nt][3] + bz1;
        }
    }
}

// ---------------------------------------------------------------------------
// bilinear v9: 128 threads, 4 warps as 2m x 2n, warp tile m64 x n64
// (fragment reuse 16 MAC/byte vs 10.7). Ring-3, ONE barrier per unit,
// i-outer/j-inner, fold per i-chunk. BT=128, 2 CTA/SM (<=256 regs/thread).
// Per-unit L1: LDSM 64KB + STS 32KB (was 96+32) — tensor becomes dominant.
// ---------------------------------------------------------------------------
template <int DI, int DJ>
__global__ void __launch_bounds__(128, 2)
bilinear_v9(const __half* __restrict__ Th, const __half* __restrict__ X1h,
            const __half* __restrict__ X2h, float* __restrict__ Y) {
    extern __shared__ __align__(16) __half sm[];
    // layout: A slots [0..3)*ABLK, B slots [3..6)*ABLK, ysum floats after
    float* ysum = (float*)(sm + 6 * ABLK);

    const int tid = threadIdx.x, lane = tid & 31, w = tid >> 5;
    const int wm = w >> 1, wn = w & 1;       // 2 x 2
    const int b0 = blockIdx.x * 128, k = blockIdx.y;
    const __half* Tk = Th + (size_t)k * DI * DJ;

    ysum[tid] = 0.f;   // 128 threads cover all 128 rows

    const int g = lane >> 3, lr = lane & 7;
    const int a_row = (g & 1) * 8 + lr, a_col = (g >> 1) * 8;
    const int b_row = (g >> 1) * 8 + lr, b_col = (g & 1) * 8;

    uint32_t a_addr[3], b_addr[3];
#pragma unroll
    for (int s = 0; s < 3; s++) {
        a_addr[s] = smem_u32(&sm[s * ABLK + (wm * 64 + a_row) * JSTR + a_col]);
        b_addr[s] = smem_u32(&sm[(3 + s) * ABLK + (wn * 64 + b_row) * JSTR + b_col]);
    }

    const int er = lane >> 2, ec = lane & 3;

    float y[2][4];
#pragma unroll
    for (int i = 0; i < 2; i++)
#pragma unroll
        for (int m = 0; m < 4; m++) y[i][m] = 0.f;

    constexpr int UNITS = (DI / 128) * (DJ / 64);
    constexpr int JCH = DJ / 64;
    float acc[4][8][4];   // m64 x n64 warp tile (128 regs)

    auto stage = [&](int u, int slot) {
        const int ich = u / JCH, j0 = (u % JCH) * 64;
        const uint32_t ao = slot * ABLK;
        const uint32_t bo = (3 + slot) * ABLK;
#pragma unroll
        for (int s = 0; s < 8; s++) {
            int t = tid + s * 128;
            int row = t >> 3, seg = (t & 7) * 8;
            cp16cg(smem_u32(&sm[ao + row * JSTR + seg]),
                   X2h + (size_t)(b0 + row) * DJ + j0 + seg);
            cp16cg(smem_u32(&sm[bo + row * JSTR + seg]),
                   Tk + (size_t)(ich * 128 + row) * DJ + j0 + seg);
        }
    };

    int s_cur = 0, s_nxt = 1;
    stage(0, 0);
    CP_COMMIT();
    for (int u = 0; u < UNITS; u++) {
        if (u + 1 < UNITS) {
            stage(u + 1, s_nxt);
            CP_COMMIT();
            cp_wait<1>();
        } else {
            cp_wait<0>();
        }
        __syncthreads();  // the ONLY barrier per unit (ring-3 safe)

        const int jc = u % JCH, ich = u / JCH;
        if (jc == 0) {
#pragma unroll
            for (int mt = 0; mt < 4; mt++)
#pragma unroll
                for (int nt = 0; nt < 8; nt++)
#pragma unroll
                    for (int q = 0; q < 4; q++) acc[mt][nt][q] = 0.f;
        }

        const uint32_t aa = a_addr[s_cur], ba = b_addr[s_cur];
#pragma unroll
        for (int ks = 0; ks < 4; ks++) {
            uint32_t br[4][4];   // 64 n-rows x 16 k
#pragma unroll
            for (int q = 0; q < 4; q++)
                ldm4(br[q], ba + (q * 16 * JSTR + ks * 16) * 2);
#pragma unroll
            for (int mt = 0; mt < 4; mt++) {
                uint32_t a[4];
                ldm4(a, aa + (mt * 16 * JSTR + ks * 16) * 2);
#pragma unroll
                for (int nt = 0; nt < 8; nt++) {
                    const uint32_t* bb = br[nt >> 1];
                    mma_f16(acc[mt][nt], a, bb[(nt & 1) * 2],
                            bb[(nt & 1) * 2 + 1]);
                }
            }
        }

        if (jc == JCH - 1) {
#pragma unroll
            for (int mt = 0; mt < 4; mt++) {
                int r = wm * 64 + mt * 16 + er;
#pragma unroll
                for (int nt = 0; nt < 8; nt++) {
                    int ii = ich * 128 + wn * 64 + nt * 8 + ec * 2;
                    __half2 xa = *(const __half2*)&X1h[(size_t)(b0 + r) * DI + ii];
                    __half2 xb = *(const __half2*)&X1h[(size_t)(b0 + r + 8) * DI + ii];
                    float2 fa = __half22float2(xa);
                    float2 fb = __half22float2(xb);
                    y[0][mt] = fmaf(acc[mt][nt][0], fa.x, y[0][mt]);
                    y[0][mt] = fmaf(acc[mt][nt][1], fa.y, y[0][mt]);
                    y[1][mt] = fmaf(acc[mt][nt][2], fb.x, y[1][mt]);
                    y[1][mt] = fmaf(acc[mt][nt][3], fb.y, y[1][mt]);
                }
            }
        }

        s_cur = s_nxt;
        if (++s_nxt == 3) s_nxt = 0;
    }

    // reduce over 4 column-quad lanes; combine the 2 n-warps via smem atomics
#pragma unroll
    for (int i = 0; i < 2; i++)
#pragma unroll
        for (int mt = 0; mt < 4; mt++) {
            y[i][mt] += __shfl_xor_sync(0xffffffffu, y[i][mt], 1);
            y[i][mt] += __shfl_xor_sync(0xffffffffu, y[i][mt], 2);
        }
    if (ec == 0) {
#pragma unroll
        for (int mt = 0; mt < 4; mt++) {
            atomicAdd(&ysum[wm * 64 + mt * 16 + er], y[0][mt]);
            atomicAdd(&ysum[wm * 64 + mt * 16 + er + 8], y[1][mt]);
        }
    }
    __syncthreads();
    {
        size_t b = (size_t)b0 + tid;
        Y[b * K_SZ + k] = ysum[tid];
    }
}

// ---------------------------------------------------------------------------
// Launch — ordered so the 4th launch (observed ncu capture slot) is bilinear1.
// ---------------------------------------------------------------------------
extern "C" void kernel_launch(void* const* d_in, const int* in_sizes, int n_in,
                              void* d_out, int out_size) {
    const int*   subj_id = (const int*)d_in[0];
    const float* subj_w  = (const float*)d_in[1];
    const int*   verb_id = (const int*)d_in[2];
    const float* verb_w  = (const float*)d_in[3];
    const int*   obj_id  = (const int*)d_in[4];
    const float* obj_w   = (const float*)d_in[5];
    const float* emb     = (const float*)d_in[6];
    const float* t1      = (const float*)d_in[7];
    const float* t2      = (const float*)d_in[8];
    const float* t3      = (const float*)d_in[9];
    const float* W1      = (const float*)d_in[10];
    const float* b1      = (const float*)d_in[11];
    const float* W2      = (const float*)d_in[12];
    const float* b2      = (const float*)d_in[13];
    const float* W3      = (const float*)d_in[14];
    const float* b3      = (const float*)d_in[15];
    float* out = (float*)d_out;

    float *pL1, *pL2, *pL3, *pY, *pR1, *pR2;
    __half *pSh, *pVh, *pOh, *pR1h, *pR2h;
    __half *pT1h, *pT2h, *pT3h, *pW1h, *pW2h, *pW3h;
    cudaGetSymbolAddress((void**)&pL1,  g_L1);
    cudaGetSymbolAddress((void**)&pL2,  g_L2);
    cudaGetSymbolAddress((void**)&pL3,  g_L3);
    cudaGetSymbolAddress((void**)&pY,   g_Y);
    cudaGetSymbolAddress((void**)&pR1,  g_R1);
    cudaGetSymbolAddress((void**)&pR2,  g_R2);
    cudaGetSymbolAddress((void**)&pSh,  g_Sh);
    cudaGetSymbolAddress((void**)&pVh,  g_Vh);
    cudaGetSymbolAddress((void**)&pOh,  g_Oh);
    cudaGetSymbolAddress((void**)&pR1h, g_R1h);
    cudaGetSymbolAddress((void**)&pR2h, g_R2h);
    cudaGetSymbolAddress((void**)&pT1h, g_T1h);
    cudaGetSymbolAddress((void**)&pT2h, g_T2h);
    cudaGetSymbolAddress((void**)&pT3h, g_T3h);
    cudaGetSymbolAddress((void**)&pW1h, g_W1h);
    cudaGetSymbolAddress((void**)&pW2h, g_W2h);
    cudaGetSymbolAddress((void**)&pW3h, g_W3h);

    const int smem_v9 = 6 * ABLK * 2 + 128 * 4;  // 111104 B
    cudaFuncSetAttribute(bilinear_v9<512, 512>,
                         cudaFuncAttributeMaxDynamicSharedMemorySize, smem_v9);
    cudaFuncSetAttribute(bilinear_v9<256, 256>,
                         cudaFuncAttributeMaxDynamicSharedMemorySize, smem_v9);

    dim3 lin_grid(B_SZ / 64, K_SZ / 128);
    dim3 bil_grid(B_SZ / 128, K_SZ);
    dim3 fin_grid(B_SZ * K_SZ / 256);

    // phase 1 — bilinear1 is launch #4 (ncu capture slot)
    embed_kernel<<<B_SZ, 128>>>(subj_id, subj_w, emb, pSh);           // 1
    embed_kernel<<<B_SZ, 128>>>(verb_id, verb_w, emb, pVh);           // 2
    f2h_kernel<<<4096, 256>>>(t1, pT1h, 256 * 512 * 512);             // 3
    bilinear_v9<512, 512><<<bil_grid, 128, smem_v9>>>(pT1h, pSh, pVh, pY);  // 4 *
    f2h_kernel<<<256, 256>>>(W1, pW1h, 256 * 1024);                   // 5
    linear_f16<<<lin_grid, 256>>>(pSh, pVh, pW1h, b1, pL1, 512);      // 6
    finish_kernel<<<fin_grid, 256>>>(pY, pL1, pR1, pR1h);             // 7

    // phase 2
    embed_kernel<<<B_SZ, 128>>>(obj_id, obj_w, emb, pOh);
    f2h_kernel<<<4096, 256>>>(t2, pT2h, 256 * 512 * 512);
    bilinear_v9<512, 512><<<bil_grid, 128, smem_v9>>>(pT2h, pVh, pOh, pY);
    f2h_kernel<<<256, 256>>>(W2, pW2h, 256 * 1024);
    linear_f16<<<lin_grid, 256>>>(pVh, pOh, pW2h, b2, pL2, 512);
    finish_kernel<<<fin_grid, 256>>>(pY, pL2, pR2, pR2h);

    // phase 3
    f2h_kernel<<<256, 256>>>(W3, pW3h, 256 * 512);
    linear_f16<<<lin_grid, 256>>>(pR1h, pR2h, pW3h, b3, pL3, 256);
    f2h_kernel<<<2048, 256>>>(t3, pT3h, 256 * 256 * 256);
    bilinear_v9<256, 256><<<bil_grid, 128, smem_v9>>>(pT3h, pR1h, pR2h, pY);
    finish_kernel<<<fin_grid, 256>>>(pY, pL3, out, pOh);
}

// round 16
// speedup vs baseline: 2.4554x; 1.0314x over previous
#include <cuda_runtime.h>
#include <cuda_fp16.h>
#include <math.h>
#include <stdint.h>

#define B_SZ 4096
#define K_SZ 256
#define N_SZ 8

// ---------------------------------------------------------------------------
// Scratch (device globals; allocations are banned)
// ---------------------------------------------------------------------------
__device__ __align__(256) float  g_Y[B_SZ * 256];    // raw bilinear output
__device__ __align__(256) float  g_R1[B_SZ * 256];
__device__ __align__(256) float  g_R2[B_SZ * 256];
__device__ __align__(256) __half g_Sh[B_SZ * 512];
__device__ __align__(256) __half g_Vh[B_SZ * 512];
__device__ __align__(256) __half g_Oh[B_SZ * 512];   // also phase-3 OUTh dump
__device__ __align__(256) __half g_R1h[B_SZ * 256];
__device__ __align__(256) __half g_R2h[B_SZ * 256];
__device__ __align__(256) __half g_T1h[256u * 512u * 512u];
__device__ __align__(256) __half g_T2h[256u * 512u * 512u];
__device__ __align__(256) __half g_T3h[256u * 256u * 256u];
__device__ __align__(256) __half g_W1h[256 * 1024];
__device__ __align__(256) __half g_W2h[256 * 1024];
__device__ __align__(256) __half g_W3h[256 * 512];

// ---------------------------------------------------------------------------
// Generic-PTX helpers (compute_103 virtual arch: no tcgen05/'a' features)
// ---------------------------------------------------------------------------
__device__ __forceinline__ uint32_t smem_u32(const void* p) {
    uint32_t a;
    asm("{ .reg .u64 t; cvta.to.shared.u64 t, %1; cvt.u32.u64 %0, t; }"
        : "=r"(a) : "l"(p));
    return a;
}
__device__ __forceinline__ void ldm4(uint32_t* r, uint32_t addr) {
    asm volatile(
        "ldmatrix.sync.aligned.m8n8.x4.shared.b16 {%0,%1,%2,%3}, [%4];"
        : "=r"(r[0]), "=r"(r[1]), "=r"(r[2]), "=r"(r[3]) : "r"(addr));
}
__device__ __forceinline__ void mma_f16(float* c, const uint32_t* a,
                                        uint32_t b0, uint32_t b1) {
    asm volatile(
        "mma.sync.aligned.m16n8k16.row.col.f32.f16.f16.f32 "
        "{%0,%1,%2,%3}, {%4,%5,%6,%7}, {%8,%9}, {%0,%1,%2,%3};"
        : "+f"(c[0]), "+f"(c[1]), "+f"(c[2]), "+f"(c[3])
        : "r"(a[0]), "r"(a[1]), "r"(a[2]), "r"(a[3]), "r"(b0), "r"(b1));
}
__device__ __forceinline__ void cp16(uint32_t dst, const void* src) {
    asm volatile("cp.async.ca.shared.global [%0], [%1], 16;"
                 :: "r"(dst), "l"(src) : "memory");
}
__device__ __forceinline__ void cp16cg(uint32_t dst, const void* src) {
    asm volatile("cp.async.cg.shared.global [%0], [%1], 16;"
                 :: "r"(dst), "l"(src) : "memory");
}
#define CP_COMMIT() asm volatile("cp.async.commit_group;" ::: "memory")
template <int N>
__device__ __forceinline__ void cp_wait() {
    asm volatile("cp.async.wait_group %0;" :: "n"(N) : "memory");
}

#define HSTR 40   // linear kernel SMEM row stride (halfs)
#define JSTR 72   // bilinear SMEM row stride (halfs): 64 data + 8 pad
#define ABLK (128 * JSTR)   // one ring slot (halfs)

// ---------------------------------------------------------------------------
// fp32 -> fp16 bulk convert
// ---------------------------------------------------------------------------
__global__ void f2h_kernel(const float* __restrict__ src,
                           __half* __restrict__ dst, int n) {
    int i = (blockIdx.x * blockDim.x + threadIdx.x) * 4;
    int stride = gridDim.x * blockDim.x * 4;
    for (; i < n; i += stride) {
        float4 v = *(const float4*)(src + i);
        ((__half2*)(dst + i))[0] = __floats2half2_rn(v.x, v.y);
        ((__half2*)(dst + i))[1] = __floats2half2_rn(v.z, v.w);
    }
}

// ---------------------------------------------------------------------------
// phrase embedding (fp16 output)
// ---------------------------------------------------------------------------
__global__ void embed_kernel(const int* __restrict__ ids,
                             const float* __restrict__ w,
                             const float* __restrict__ emb,
                             __half* __restrict__ outh) {
    int b = blockIdx.x;
    int t = threadIdx.x;
    const float4* emb4 = (const float4*)emb;
    float4 acc = make_float4(0.f, 0.f, 0.f, 0.f);
#pragma unroll
    for (int n = 0; n < N_SZ; n++) {
        int   id = __ldg(&ids[b * N_SZ + n]);
        float wn = __ldg(&w[b * N_SZ + n]);
        float4 e = __ldg(&emb4[(size_t)id * 128 + t]);
        acc.x = fmaf(wn, e.x, acc.x);
        acc.y = fmaf(wn, e.y, acc.y);
        acc.z = fmaf(wn, e.z, acc.z);
        acc.w = fmaf(wn, e.w, acc.w);
    }
    ((__half2*)outh)[(size_t)b * 256 + t * 2]     = __floats2half2_rn(acc.x, acc.y);
    ((__half2*)outh)[(size_t)b * 256 + t * 2 + 1] = __floats2half2_rn(acc.z, acc.w);
}

// ---------------------------------------------------------------------------
// linear + finish fused: v = tanh(Y[b,k] + [X1;X2][b,:].W[k,:] + bias[k])
// writes OUT (fp32) and OUTh (fp16). CTA tile 64b x 128k, 8 warps (2x4).
// ---------------------------------------------------------------------------
__global__ void __launch_bounds__(256, 2)
linear_finish(const __half* __restrict__ X1h, const __half* __restrict__ X2h,
              const __half* __restrict__ Wh, const float* __restrict__ bias,
              const float* __restrict__ Y,
              float* __restrict__ OUT, __half* __restrict__ OUTh, int Dh) {
    __shared__ __align__(16) __half Abuf[2][64 * HSTR];
    __shared__ __align__(16) __half Bbuf[2][128 * HSTR];

    const int tid = threadIdx.x, lane = tid & 31, w = tid >> 5;
    const int wm = w >> 2, wn = w & 3;
    const int b0 = blockIdx.x * 64, k0 = blockIdx.y * 128;
    const int g = lane >> 3, lr = lane & 7;
    const int a_row = (g & 1) * 8 + lr, a_col = (g >> 1) * 8;
    const int b_row = (g >> 1) * 8 + lr, b_col = (g & 1) * 8;

    uint32_t a_addr[2], b_addr[2];
#pragma unroll
    for (int buf = 0; buf < 2; buf++) {
        a_addr[buf] = smem_u32(&Abuf[buf][(wm * 32 + a_row) * HSTR + a_col]);
        b_addr[buf] = smem_u32(&Bbuf[buf][(wn * 32 + b_row) * HSTR + b_col]);
    }

    float acc[2][4][4];
#pragma unroll
    for (int mt = 0; mt < 2; mt++)
#pragma unroll
        for (int nt = 0; nt < 4; nt++)
#pragma unroll
            for (int q = 0; q < 4; q++) acc[mt][nt][q] = 0.f;

    const int HC = Dh / 32;
    const int NC = 2 * HC;
    const int srow = tid >> 2, sseg = (tid & 3) * 8;

    auto stage = [&](int c, int nb) {
        const __half* Asrc = (c < HC) ? X1h : X2h;
        int dof = ((c < HC) ? c : c - HC) * 32;
        cp16(smem_u32(&Abuf[nb][srow * HSTR + sseg]),
             Asrc + (size_t)(b0 + srow) * Dh + dof + sseg);
        cp16(smem_u32(&Bbuf[nb][srow * HSTR + sseg]),
             Wh + (size_t)(k0 + srow) * (2 * Dh) + c * 32 + sseg);
        cp16(smem_u32(&Bbuf[nb][(srow + 64) * HSTR + sseg]),
             Wh + (size_t)(k0 + srow + 64) * (2 * Dh) + c * 32 + sseg);
    };

    stage(0, 0);
    CP_COMMIT();
    for (int c = 0; c < NC; c++) {
        if (c + 1 < NC) {
            stage(c + 1, (c + 1) & 1);
            CP_COMMIT();
            cp_wait<1>();
        } else {
            cp_wait<0>();
        }
        __syncthreads();
        int buf = c & 1;
#pragma unroll
        for (int ks = 0; ks < 2; ks++) {
            uint32_t a[2][4];
            ldm4(a[0], a_addr[buf] + (0 * 16 * HSTR + ks * 16) * 2);
            ldm4(a[1], a_addr[buf] + (1 * 16 * HSTR + ks * 16) * 2);
            uint32_t br[2][4];
            ldm4(br[0], b_addr[buf] + (ks * 16) * 2);
            ldm4(br[1], b_addr[buf] + (16 * HSTR + ks * 16) * 2);
#pragma unroll
            for (int mt = 0; mt < 2; mt++)
#pragma unroll
                for (int nt = 0; nt < 4; nt++) {
                    const uint32_t* bb = br[nt >> 1];
                    mma_f16(acc[mt][nt], a[mt], bb[(nt & 1) * 2],
                            bb[(nt & 1) * 2 + 1]);
                }
        }
        __syncthreads();
    }

    const int er = lane >> 2, ec = lane & 3;
#pragma unroll
    for (int mt = 0; mt < 2; mt++) {
        size_t r0 = (size_t)(b0 + wm * 32 + mt * 16 + er);
        size_t r1 = r0 + 8;
#pragma unroll
        for (int nt = 0; nt < 4; nt++) {
            int kk = k0 + wn * 32 + nt * 8 + ec * 2;
            float bz0 = __ldg(&bias[kk]), bz1 = __ldg(&bias[kk + 1]);
            float v00 = tanhf(acc[mt][nt][0] + bz0 + Y[r0 * K_SZ + kk]);
            float v01 = tanhf(acc[mt][nt][1] + bz1 + Y[r0 * K_SZ + kk + 1]);
            float v10 = tanhf(acc[mt][nt][2] + bz0 + Y[r1 * K_SZ + kk]);
            float v11 = tanhf(acc[mt][nt][3] + bz1 + Y[r1 * K_SZ + kk + 1]);
            OUT[r0 * K_SZ + kk]     = v00;
            OUT[r0 * K_SZ + kk + 1] = v01;
            OUT[r1 * K_SZ + kk]     = v10;
            OUT[r1 * K_SZ + kk + 1] = v11;
            *(__half2*)&OUTh[r0 * K_SZ + kk] = __floats2half2_rn(v00, v01);
            *(__half2*)&OUTh[r1 * K_SZ + kk] = __floats2half2_rn(v10, v11);
        }
    }
}

// ---------------------------------------------------------------------------
// bilinear v10: v9 (128 thr, 4 warps 2m x 2n, warp tile m64 x n64, ring-3,
// ONE barrier/unit, BT=128, 2 CTA/SM) + per-warp ks-stagger to desync
// post-barrier LDSM/HMMA bursts (fp32 add reorder only; bit-safe vs gate).
// ---------------------------------------------------------------------------
template <int DI, int DJ>
__global__ void __launch_bounds__(128, 2)
bilinear_v10(const __half* __restrict__ Th, const __half* __restrict__ X1h,
             const __half* __restrict__ X2h, float* __restrict__ Y) {
    extern __shared__ __align__(16) __half sm[];
    float* ysum = (float*)(sm + 6 * ABLK);

    const int tid = threadIdx.x, lane = tid & 31, w = tid >> 5;
    const int wm = w >> 1, wn = w & 1;       // 2 x 2
    const int b0 = blockIdx.x * 128, k = blockIdx.y;
    const __half* Tk = Th + (size_t)k * DI * DJ;

    ysum[tid] = 0.f;

    const int g = lane >> 3, lr = lane & 7;
    const int a_row = (g & 1) * 8 + lr, a_col = (g >> 1) * 8;
    const int b_row = (g >> 1) * 8 + lr, b_col = (g & 1) * 8;

    uint32_t a_addr[3], b_addr[3];
#pragma unroll
    for (int s = 0; s < 3; s++) {
        a_addr[s] = smem_u32(&sm[s * ABLK + (wm * 64 + a_row) * JSTR + a_col]);
        b_addr[s] = smem_u32(&sm[(3 + s) * ABLK + (wn * 64 + b_row) * JSTR + b_col]);
    }

    const int er = lane >> 2, ec = lane & 3;

    float y[2][4];
#pragma unroll
    for (int i = 0; i < 2; i++)
#pragma unroll
        for (int m = 0; m < 4; m++) y[i][m] = 0.f;

    constexpr int UNITS = (DI / 128) * (DJ / 64);
    constexpr int JCH = DJ / 64;
    float acc[4][8][4];   // m64 x n64 warp tile

    auto stage = [&](int u, int slot) {
        const int ich = u / JCH, j0 = (u % JCH) * 64;
        const uint32_t ao = slot * ABLK;
        const uint32_t bo = (3 + slot) * ABLK;
#pragma unroll
        for (int s = 0; s < 8; s++) {
            int t = tid + s * 128;
            int row = t >> 3, seg = (t & 7) * 8;
            cp16cg(smem_u32(&sm[ao + row * JSTR + seg]),
                   X2h + (size_t)(b0 + row) * DJ + j0 + seg);
            cp16cg(smem_u32(&sm[bo + row * JSTR + seg]),
                   Tk + (size_t)(ich * 128 + row) * DJ + j0 + seg);
        }
    };

    int s_cur = 0, s_nxt = 1;
    stage(0, 0);
    CP_COMMIT();
    for (int u = 0; u < UNITS; u++) {
        if (u + 1 < UNITS) {
            stage(u + 1, s_nxt);
            CP_COMMIT();
            cp_wait<1>();
        } else {
            cp_wait<0>();
        }
        __syncthreads();  // the ONLY barrier per unit (ring-3 safe)

        const int jc = u % JCH, ich = u / JCH;
        if (jc == 0) {
#pragma unroll
            for (int mt = 0; mt < 4; mt++)
#pragma unroll
                for (int nt = 0; nt < 8; nt++)
#pragma unroll
                    for (int q = 0; q < 4; q++) acc[mt][nt][q] = 0.f;
        }

        const uint32_t aa = a_addr[s_cur], ba = b_addr[s_cur];
#pragma unroll
        for (int kk2 = 0; kk2 < 4; kk2++) {
            const int ks = (kk2 + w) & 3;  // per-warp stagger
            uint32_t br[4][4];
#pragma unroll
            for (int q = 0; q < 4; q++)
                ldm4(br[q], ba + (q * 16 * JSTR + ks * 16) * 2);
#pragma unroll
            for (int mt = 0; mt < 4; mt++) {
                uint32_t a[4];
                ldm4(a, aa + (mt * 16 * JSTR + ks * 16) * 2);
#pragma unroll
                for (int nt = 0; nt < 8; nt++) {
                    const uint32_t* bb = br[nt >> 1];
                    mma_f16(acc[mt][nt], a, bb[(nt & 1) * 2],
                            bb[(nt & 1) * 2 + 1]);
                }
            }
        }

        if (jc == JCH - 1) {
#pragma unroll
            for (int mt = 0; mt < 4; mt++) {
                int r = wm * 64 + mt * 16 + er;
#pragma unroll
                for (int nt = 0; nt < 8; nt++) {
                    int ii = ich * 128 + wn * 64 + nt * 8 + ec * 2;
                    __half2 xa = *(const __half2*)&X1h[(size_t)(b0 + r) * DI + ii];
                    __half2 xb = *(const __half2*)&X1h[(size_t)(b0 + r + 8) * DI + ii];
                    float2 fa = __half22float2(xa);
                    float2 fb = __half22float2(xb);
                    y[0][mt] = fmaf(acc[mt][nt][0], fa.x, y[0][mt]);
                    y[0][mt] = fmaf(acc[mt][nt][1], fa.y, y[0][mt]);
                    y[1][mt] = fmaf(acc[mt][nt][2], fb.x, y[1][mt]);
                    y[1][mt] = fmaf(acc[mt][nt][3], fb.y, y[1][mt]);
                }
            }
        }

        s_cur = s_nxt;
        if (++s_nxt == 3) s_nxt = 0;
    }

    // reduce over 4 column-quad lanes; combine the 2 n-warps via smem atomics
#pragma unroll
    for (int i = 0; i < 2; i++)
#pragma unroll
        for (int mt = 0; mt < 4; mt++) {
            y[i][mt] += __shfl_xor_sync(0xffffffffu, y[i][mt], 1);
            y[i][mt] += __shfl_xor_sync(0xffffffffu, y[i][mt], 2);
        }
    if (ec == 0) {
#pragma unroll
        for (int mt = 0; mt < 4; mt++) {
            atomicAdd(&ysum[wm * 64 + mt * 16 + er], y[0][mt]);
            atomicAdd(&ysum[wm * 64 + mt * 16 + er + 8], y[1][mt]);
        }
    }
    __syncthreads();
    {
        size_t b = (size_t)b0 + tid;
        Y[b * K_SZ + k] = ysum[tid];
    }
}

// ---------------------------------------------------------------------------
// Launch — ordered so the 4th launch (observed ncu capture slot) is bilinear1.
// ---------------------------------------------------------------------------
extern "C" void kernel_launch(void* const* d_in, const int* in_sizes, int n_in,
                              void* d_out, int out_size) {
    const int*   subj_id = (const int*)d_in[0];
    const float* subj_w  = (const float*)d_in[1];
    const int*   verb_id = (const int*)d_in[2];
    const float* verb_w  = (const float*)d_in[3];
    const int*   obj_id  = (const int*)d_in[4];
    const float* obj_w   = (const float*)d_in[5];
    const float* emb     = (const float*)d_in[6];
    const float* t1      = (const float*)d_in[7];
    const float* t2      = (const float*)d_in[8];
    const float* t3      = (const float*)d_in[9];
    const float* W1      = (const float*)d_in[10];
    const float* b1      = (const float*)d_in[11];
    const float* W2      = (const float*)d_in[12];
    const float* b2      = (const float*)d_in[13];
    const float* W3      = (const float*)d_in[14];
    const float* b3      = (const float*)d_in[15];
    float* out = (float*)d_out;

    float *pY, *pR1, *pR2;
    __half *pSh, *pVh, *pOh, *pR1h, *pR2h;
    __half *pT1h, *pT2h, *pT3h, *pW1h, *pW2h, *pW3h;
    cudaGetSymbolAddress((void**)&pY,   g_Y);
    cudaGetSymbolAddress((void**)&pR1,  g_R1);
    cudaGetSymbolAddress((void**)&pR2,  g_R2);
    cudaGetSymbolAddress((void**)&pSh,  g_Sh);
    cudaGetSymbolAddress((void**)&pVh,  g_Vh);
    cudaGetSymbolAddress((void**)&pOh,  g_Oh);
    cudaGetSymbolAddress((void**)&pR1h, g_R1h);
    cudaGetSymbolAddress((void**)&pR2h, g_R2h);
    cudaGetSymbolAddress((void**)&pT1h, g_T1h);
    cudaGetSymbolAddress((void**)&pT2h, g_T2h);
    cudaGetSymbolAddress((void**)&pT3h, g_T3h);
    cudaGetSymbolAddress((void**)&pW1h, g_W1h);
    cudaGetSymbolAddress((void**)&pW2h, g_W2h);
    cudaGetSymbolAddress((void**)&pW3h, g_W3h);

    const int smem_v10 = 6 * ABLK * 2 + 128 * 4;  // 111104 B
    cudaFuncSetAttribute(bilinear_v10<512, 512>,
                         cudaFuncAttributeMaxDynamicSharedMemorySize, smem_v10);
    cudaFuncSetAttribute(bilinear_v10<256, 256>,
                         cudaFuncAttributeMaxDynamicSharedMemorySize, smem_v10);

    dim3 lin_grid(B_SZ / 64, K_SZ / 128);
    dim3 bil_grid(B_SZ / 128, K_SZ);

    // phase 1 — bilinear1 is launch #4 (ncu capture slot)
    embed_kernel<<<B_SZ, 128>>>(subj_id, subj_w, emb, pSh);            // 1
    embed_kernel<<<B_SZ, 128>>>(verb_id, verb_w, emb, pVh);            // 2
    f2h_kernel<<<4096, 256>>>(t1, pT1h, 256 * 512 * 512);              // 3
    bilinear_v10<512, 512><<<bil_grid, 128, smem_v10>>>(pT1h, pSh, pVh, pY); // 4*
    f2h_kernel<<<256, 256>>>(W1, pW1h, 256 * 1024);                    // 5
    linear_finish<<<lin_grid, 256>>>(pSh, pVh, pW1h, b1, pY, pR1, pR1h, 512);

    // phase 2
    embed_kernel<<<B_SZ, 128>>>(obj_id, obj_w, emb, pOh);
    f2h_kernel<<<4096, 256>>>(t2, pT2h, 256 * 512 * 512);
    bilinear_v10<512, 512><<<bil_grid, 128, smem_v10>>>(pT2h, pVh, pOh, pY);
    f2h_kernel<<<256, 256>>>(W2, pW2h, 256 * 1024);
    linear_finish<<<lin_grid, 256>>>(pVh, pOh, pW2h, b2, pY, pR2, pR2h, 512);

    // phase 3 — OUTh must not alias X1h/X2h; dump to g_Oh (free by now)
    f2h_kernel<<<256, 256>>>(W3, pW3h, 256 * 512);
    f2h_kernel<<<2048, 256>>>(t3, pT3h, 256 * 256 * 256);
    bilinear_v10<256, 256><<<bil_grid, 128, smem_v10>>>(pT3h, pR1h, pR2h, pY);
    linear_finish<<<lin_grid, 256>>>(pR1h, pR2h, pW3h, b3, pY, out, pOh, 256);
}